// round 1
// baseline (speedup 1.0000x reference)
#include <cuda_runtime.h>
#include <cstdint>

#define H   1024
#define NB  16
#define TSTEPS 256
#define BT  4096      // B*T
#define N1  4096      // 4*H (gate pre-activations)
#define NV  32000

typedef unsigned long long u64;

// ---------------- scratch (device globals; no allocations allowed) ----------
__device__ float g_xall[(size_t)BT * N1];   // [b*T+t][4H] gate pre-activations (64 MB)
__device__ float g_hs[(size_t)BT * H];      // [b*T+t][H] hidden states (16 MB)
__device__ float g_h[H * NB];               // current h, layout [k][b]
__device__ unsigned g_bar;                  // grid barrier counter

// ---------------- packed f32x2 helpers (Blackwell 2x fp32 path) -------------
__device__ __forceinline__ u64 pk2(float lo, float hi) {
    u64 r; asm("mov.b64 %0, {%1,%2};" : "=l"(r) : "f"(lo), "f"(hi)); return r;
}
__device__ __forceinline__ void fma2(u64 &d, u64 a, u64 b) {
    asm("fma.rn.f32x2 %0, %1, %2, %0;" : "+l"(d) : "l"(a), "l"(b));
}
__device__ __forceinline__ void upk2(float &lo, float &hi, u64 v) {
    asm("mov.b64 {%0,%1}, %2;" : "=f"(lo), "=f"(hi) : "l"(v));
}

// ---------------- tiled fp32x2 GEMM: phase 1 (embed gather + 4 gate GEMMs) --
#define BM 128
#define BN 128
#define BK 16

__global__ void __launch_bounds__(256) gemm_p1(
    const int* __restrict__ tokens, const float* __restrict__ emb,
    const float* __restrict__ w_f, const float* __restrict__ w_i,
    const float* __restrict__ w_c, const float* __restrict__ w_o,
    const float* __restrict__ b_f, const float* __restrict__ b_i,
    const float* __restrict__ b_c, const float* __restrict__ b_o)
{
    __shared__ float As[BK][BM + 4];
    __shared__ float Bs[BK][BN];
    const int tid = threadIdx.x;
    const int m0 = blockIdx.y * BM;
    const int n0 = blockIdx.x * BN;
    const int g   = n0 >> 10;       // which gate (tile never straddles gates)
    const int nloc = n0 & 1023;
    const float* W    = (g == 0) ? w_f : (g == 1) ? w_i : (g == 2) ? w_c : w_o;
    const float* bias = (g == 0) ? b_f : (g == 1) ? b_i : (g == 2) ? b_c : b_o;

    // A (gathered embedding rows): thread loads 8 k-contiguous floats of one row
    const int ar = tid & 127;
    const int kh = (tid >> 7) * 8;
    const float* aptr = emb + (size_t)__ldg(&tokens[m0 + ar]) * H + kh;
    // B: two float4 per thread, coalesced along n
    const int brow0 = tid >> 5;           // 0..7
    const int bcol  = (tid & 31) * 4;
    const float* bptr = W + nloc + bcol;

    float4 arg0, arg1, brg0, brg1;
    arg0 = *(const float4*)(aptr + 0);
    arg1 = *(const float4*)(aptr + 4);
    brg0 = *(const float4*)(bptr + (size_t)brow0 * H);
    brg1 = *(const float4*)(bptr + (size_t)(brow0 + 8) * H);

    u64 acc[8][4];
    #pragma unroll
    for (int i = 0; i < 8; i++)
        #pragma unroll
        for (int j = 0; j < 4; j++) acc[i][j] = 0ull;

    const int ty = tid >> 4, tx = tid & 15;

    for (int kt = 0; kt < H / BK; kt++) {
        #pragma unroll
        for (int i = 0; i < 4; i++) As[kh + i][ar]     = ((float*)&arg0)[i];
        #pragma unroll
        for (int i = 0; i < 4; i++) As[kh + 4 + i][ar] = ((float*)&arg1)[i];
        *(float4*)&Bs[brow0][bcol]     = brg0;
        *(float4*)&Bs[brow0 + 8][bcol] = brg1;
        __syncthreads();
        if (kt + 1 < H / BK) {
            const float* ap = aptr + (kt + 1) * BK;
            arg0 = *(const float4*)(ap);
            arg1 = *(const float4*)(ap + 4);
            const float* bp = bptr + (size_t)((kt + 1) * BK) * H;
            brg0 = *(const float4*)(bp + (size_t)brow0 * H);
            brg1 = *(const float4*)(bp + (size_t)(brow0 + 8) * H);
        }
        #pragma unroll
        for (int k = 0; k < BK; k++) {
            float4 a0 = *(const float4*)&As[k][ty * 8];
            float4 a1 = *(const float4*)&As[k][ty * 8 + 4];
            float4 b0 = *(const float4*)&Bs[k][tx * 8];
            float4 b1 = *(const float4*)&Bs[k][tx * 8 + 4];
            u64 bp4[4] = { pk2(b0.x, b0.y), pk2(b0.z, b0.w),
                           pk2(b1.x, b1.y), pk2(b1.z, b1.w) };
            float am[8] = {a0.x, a0.y, a0.z, a0.w, a1.x, a1.y, a1.z, a1.w};
            #pragma unroll
            for (int i = 0; i < 8; i++) {
                u64 aa = pk2(am[i], am[i]);
                #pragma unroll
                for (int j = 0; j < 4; j++) fma2(acc[i][j], aa, bp4[j]);
            }
        }
        __syncthreads();
    }
    float bv[8];
    *(float4*)&bv[0] = *(const float4*)&bias[nloc + tx * 8];
    *(float4*)&bv[4] = *(const float4*)&bias[nloc + tx * 8 + 4];
    #pragma unroll
    for (int i = 0; i < 8; i++) {
        float o[8];
        #pragma unroll
        for (int j = 0; j < 4; j++) upk2(o[2*j], o[2*j+1], acc[i][j]);
        #pragma unroll
        for (int jj = 0; jj < 8; jj++) o[jj] += bv[jj];
        float* crow = g_xall + (size_t)(m0 + ty * 8 + i) * N1 + n0 + tx * 8;
        *(float4*)crow       = *(float4*)&o[0];
        *(float4*)(crow + 4) = *(float4*)&o[4];
    }
}

// ---------------- phase 3: logits = hs @ w_out + b_out ----------------------
__global__ void __launch_bounds__(256) gemm_p3(
    const float* __restrict__ w_out, const float* __restrict__ b_out,
    float* __restrict__ out)
{
    __shared__ float As[BK][BM + 4];
    __shared__ float Bs[BK][BN];
    const int tid = threadIdx.x;
    const int m0 = blockIdx.y * BM;
    const int n0 = blockIdx.x * BN;

    const int ar = tid & 127;
    const int kh = (tid >> 7) * 8;
    const float* aptr = g_hs + (size_t)(m0 + ar) * H + kh;
    const int brow0 = tid >> 5;
    const int bcol  = (tid & 31) * 4;
    const float* bptr = w_out + n0 + bcol;

    float4 arg0, arg1, brg0, brg1;
    arg0 = *(const float4*)(aptr + 0);
    arg1 = *(const float4*)(aptr + 4);
    brg0 = *(const float4*)(bptr + (size_t)brow0 * NV);
    brg1 = *(const float4*)(bptr + (size_t)(brow0 + 8) * NV);

    u64 acc[8][4];
    #pragma unroll
    for (int i = 0; i < 8; i++)
        #pragma unroll
        for (int j = 0; j < 4; j++) acc[i][j] = 0ull;

    const int ty = tid >> 4, tx = tid & 15;

    for (int kt = 0; kt < H / BK; kt++) {
        #pragma unroll
        for (int i = 0; i < 4; i++) As[kh + i][ar]     = ((float*)&arg0)[i];
        #pragma unroll
        for (int i = 0; i < 4; i++) As[kh + 4 + i][ar] = ((float*)&arg1)[i];
        *(float4*)&Bs[brow0][bcol]     = brg0;
        *(float4*)&Bs[brow0 + 8][bcol] = brg1;
        __syncthreads();
        if (kt + 1 < H / BK) {
            const float* ap = aptr + (kt + 1) * BK;
            arg0 = *(const float4*)(ap);
            arg1 = *(const float4*)(ap + 4);
            const float* bp = bptr + (size_t)((kt + 1) * BK) * NV;
            brg0 = *(const float4*)(bp + (size_t)brow0 * NV);
            brg1 = *(const float4*)(bp + (size_t)(brow0 + 8) * NV);
        }
        #pragma unroll
        for (int k = 0; k < BK; k++) {
            float4 a0 = *(const float4*)&As[k][ty * 8];
            float4 a1 = *(const float4*)&As[k][ty * 8 + 4];
            float4 b0 = *(const float4*)&Bs[k][tx * 8];
            float4 b1 = *(const float4*)&Bs[k][tx * 8 + 4];
            u64 bp4[4] = { pk2(b0.x, b0.y), pk2(b0.z, b0.w),
                           pk2(b1.x, b1.y), pk2(b1.z, b1.w) };
            float am[8] = {a0.x, a0.y, a0.z, a0.w, a1.x, a1.y, a1.z, a1.w};
            #pragma unroll
            for (int i = 0; i < 8; i++) {
                u64 aa = pk2(am[i], am[i]);
                #pragma unroll
                for (int j = 0; j < 4; j++) fma2(acc[i][j], aa, bp4[j]);
            }
        }
        __syncthreads();
    }
    float bv[8];
    *(float4*)&bv[0] = *(const float4*)&b_out[n0 + tx * 8];
    *(float4*)&bv[4] = *(const float4*)&b_out[n0 + tx * 8 + 4];
    #pragma unroll
    for (int i = 0; i < 8; i++) {
        float o[8];
        #pragma unroll
        for (int j = 0; j < 4; j++) upk2(o[2*j], o[2*j+1], acc[i][j]);
        #pragma unroll
        for (int jj = 0; jj < 8; jj++) o[jj] += bv[jj];
        float* crow = out + (size_t)(m0 + ty * 8 + i) * NV + n0 + tx * 8;
        *(float4*)crow       = *(float4*)&o[0];
        *(float4*)(crow + 4) = *(float4*)&o[4];
    }
}

// ---------------- phase 2: persistent recurrent kernel ----------------------
#define REC_CTAS 128
#define REC_THREADS 256
// smem: U slice [1024][32] + h staged [1024][16] + reduce [8][32][16]
#define SMEM_REC_FLOATS (1024*32 + 1024*16 + 8*32*16)
#define SMEM_REC_BYTES  (SMEM_REC_FLOATS * 4)

__global__ void __launch_bounds__(REC_THREADS, 1) lstm_rec(
    const float* __restrict__ u_f, const float* __restrict__ u_i,
    const float* __restrict__ u_c, const float* __restrict__ u_o)
{
    extern __shared__ float sm[];
    float* Us  = sm;                  // [k][32 gate-cols of this CTA]
    float* hsm = sm + 1024 * 32;      // [k][b]
    float* red = hsm + 1024 * 16;     // [ks][32][16]
    const int tid = threadIdx.x;
    const int cta = blockIdx.x;

    // cache this CTA's U slice (4 gates x 8 h-cols) in smem — persistent
    {
        const float* umat[4] = {u_f, u_i, u_c, u_o};
        for (int i = tid; i < 1024 * 32; i += REC_THREADS) {
            int k = i >> 5, cc = i & 31;
            int gg = cc >> 3, jl = cc & 7;
            Us[i] = umat[gg][(size_t)k * H + cta * 8 + jl];
        }
    }
    __syncthreads();

    const int c  = tid & 31;   // gate-col within slice
    const int ks = tid >> 5;   // k-slice (8 slices of 128)
    float creg = 0.f;          // cell state owned by gate threads (tid<128)
    const u64* hsm8 = (const u64*)hsm;

    for (int t = 0; t < TSTEPS; t++) {
        // prefetch gate pre-activations (independent of h) — hides L2/DRAM lat
        float pre[4];
        if (tid < 128) {
            int jloc = tid >> 4, b = tid & 15;
            size_t row = (size_t)(b * TSTEPS + t) * N1 + cta * 8 + jloc;
            #pragma unroll
            for (int gg = 0; gg < 4; gg++) pre[gg] = __ldg(&g_xall[row + gg * 1024]);
        }
        // stage h (written by other CTAs last step) — must bypass L1 (.cg)
        {
            const float4* gh4 = (const float4*)g_h;
            float4* h4 = (float4*)hsm;
            for (int i = tid; i < H * NB / 4; i += REC_THREADS)
                h4[i] = __ldcg(gh4 + i);
        }
        __syncthreads();

        // partial dot products: thread owns 1 gate-col x 16 batches over 128 k
        u64 acc2[8];
        #pragma unroll
        for (int i = 0; i < 8; i++) acc2[i] = 0ull;
        {
            const int kbeg = ks * 128;
            #pragma unroll 4
            for (int k = kbeg; k < kbeg + 128; k++) {
                float u = Us[k * 32 + c];
                u64 uu = pk2(u, u);
                const u64* hp = hsm8 + (size_t)k * 8;
                #pragma unroll
                for (int i = 0; i < 8; i++) fma2(acc2[i], uu, hp[i]);
            }
        }
        {
            float* rp = red + ((ks * 32 + c) << 4);
            #pragma unroll
            for (int i = 0; i < 8; i++) upk2(rp[2*i], rp[2*i+1], acc2[i]);
        }
        __syncthreads();

        // reduce k-slices + gate nonlinearity + state update (128 threads)
        if (tid < 128) {
            int jloc = tid >> 4, b = tid & 15;
            float s[4];
            #pragma unroll
            for (int gg = 0; gg < 4; gg++) {
                int cc = gg * 8 + jloc;
                float v = 0.f;
                #pragma unroll
                for (int kk = 0; kk < 8; kk++) v += red[((kk * 32 + cc) << 4) + b];
                s[gg] = v + pre[gg];
            }
            float ft   = 1.f / (1.f + expf(-s[0]));
            float it   = 1.f / (1.f + expf(-s[1]));
            float cand = tanhf(s[2]);
            float ot   = 1.f / (1.f + expf(-s[3]));
            creg = ft * creg + it * cand;
            float hv = ot * tanhf(creg);
            int jglob = cta * 8 + jloc;
            g_h[jglob * NB + b] = hv;
            g_hs[(size_t)(b * TSTEPS + t) * H + jglob] = hv;
        }

        // grid barrier (monotonic counter; init kernel zeroes it every launch)
        __syncthreads();
        if (tid == 0) {
            __threadfence();
            atomicAdd(&g_bar, 1u);
            unsigned target = (unsigned)(REC_CTAS * (t + 1));
            while (*(volatile unsigned*)&g_bar < target) __nanosleep(32);
            __threadfence();
        }
        __syncthreads();
    }
}

__global__ void init_kernel() {
    int i = blockIdx.x * blockDim.x + threadIdx.x;
    if (i == 0) g_bar = 0u;
    if (i < H * NB) g_h[i] = 0.f;
}

// ---------------- launch ----------------------------------------------------
extern "C" void kernel_launch(void* const* d_in, const int* in_sizes, int n_in,
                              void* d_out, int out_size) {
    const int*   tokens = (const int*)d_in[0];
    const float* emb    = (const float*)d_in[1];
    const float* w_f = (const float*)d_in[2];
    const float* u_f = (const float*)d_in[3];
    const float* b_f = (const float*)d_in[4];
    const float* w_i = (const float*)d_in[5];
    const float* u_i = (const float*)d_in[6];
    const float* b_i = (const float*)d_in[7];
    const float* w_c = (const float*)d_in[8];
    const float* u_c = (const float*)d_in[9];
    const float* b_c = (const float*)d_in[10];
    const float* w_o = (const float*)d_in[11];
    const float* u_o = (const float*)d_in[12];
    const float* b_o = (const float*)d_in[13];
    const float* w_out = (const float*)d_in[14];
    const float* b_out = (const float*)d_in[15];
    float* out = (float*)d_out;

    cudaFuncSetAttribute(lstm_rec, cudaFuncAttributeMaxDynamicSharedMemorySize,
                         SMEM_REC_BYTES);

    init_kernel<<<64, 256>>>();
    gemm_p1<<<dim3(N1 / BN, BT / BM), 256>>>(tokens, emb, w_f, w_i, w_c, w_o,
                                             b_f, b_i, b_c, b_o);
    lstm_rec<<<REC_CTAS, REC_THREADS, SMEM_REC_BYTES>>>(u_f, u_i, u_c, u_o);
    gemm_p3<<<dim3(NV / BN, BT / BM), 256>>>(w_out, b_out, out);
}

// round 5
// speedup vs baseline: 1.7529x; 1.7529x over previous
#include <cuda_runtime.h>
#include <cuda_fp16.h>
#include <cstdint>

#define H   1024
#define NB  16
#define TSTEPS 256
#define BT  4096      // B*T
#define N1  4096      // 4*H
#define NV  32000
#define K2  2048      // [Ah | Al] split-K

typedef unsigned long long u64;

// ---------------- scratch (device globals; no allocations allowed) ----------
__device__ float g_xall[(size_t)BT * N1];       // gate pre-activations (64 MB)
__device__ float g_hs[(size_t)BT * H];          // hidden states fp32 (16 MB)
__device__ float g_h[H * NB];                   // current h [k][b]
__device__ unsigned g_bar;                      // grid barrier
__device__ __half g_a2h[(size_t)BT * K2];       // [m][Ah|Al] fp16 (16.8 MB)
__device__ __half g_b2h[(size_t)K2 * NV];       // [Bh;Bh] fp16 (131 MB)

// ---------------- packed f32x2 helpers --------------------------------------
__device__ __forceinline__ u64 pk2(float lo, float hi) {
    u64 r; asm("mov.b64 %0, {%1,%2};" : "=l"(r) : "f"(lo), "f"(hi)); return r;
}
__device__ __forceinline__ void fma2(u64 &d, u64 a, u64 b) {
    asm("fma.rn.f32x2 %0, %1, %2, %0;" : "+l"(d) : "l"(a), "l"(b));
}
__device__ __forceinline__ void upk2(float &lo, float &hi, u64 v) {
    asm("mov.b64 {%0,%1}, %2;" : "=f"(lo), "=f"(hi) : "l"(v));
}

__device__ __forceinline__ uint32_t smem_u32(const void* p) {
    uint32_t a;
    asm("{ .reg .u64 t; cvta.to.shared.u64 t, %1; cvt.u32.u64 %0, t; }"
        : "=r"(a) : "l"(p));
    return a;
}

// ---------------- conversion kernels ----------------------------------------
__global__ void conv_w2(const float* __restrict__ w) {
    size_t idx = (size_t)blockIdx.x * blockDim.x + threadIdx.x;
    if (idx >= (size_t)H * NV) return;
    __half hv = __float2half(w[idx]);
    g_b2h[idx] = hv;                       // rows 0..1023: Bh (for Ah)
    g_b2h[idx + (size_t)H * NV] = hv;      // rows 1024..2047: Bh (for Al)
}

__global__ void conv_a2() {
    size_t idx = (size_t)blockIdx.x * blockDim.x + threadIdx.x;
    if (idx >= (size_t)BT * H) return;
    size_t m = idx >> 10, k = idx & 1023;
    float x = g_hs[idx];
    __half hi = __float2half(x);
    __half lo = __float2half(x - __half2float(hi));
    __half* row = g_a2h + m * K2;
    row[k] = hi; row[k + 1024] = lo;
}

// ---------------- phase 3: mma.sync fp16 GEMM 256x128x32, 4-stage cp.async --
#define P3_BM 256
#define P3_BN 128
#define P3_BK 32
#define P3_STAGES 4
#define A_STRIDE 40                       // halves (80 B, pad 32->40)
#define B_STRIDE 136                      // halves (272 B, pad 128->136)
#define A_ST_BYTES (P3_BM * A_STRIDE * 2) // 20480
#define B_ST_BYTES (P3_BK * B_STRIDE * 2) // 8704
#define STAGE_BYTES (A_ST_BYTES + B_ST_BYTES)
#define P3_SMEM (P3_STAGES * STAGE_BYTES) // 116736
#define P3_ITERS (K2 / P3_BK)             // 64

__device__ __forceinline__ void cp16(uint32_t dst, const void* src) {
    asm volatile("cp.async.cg.shared.global [%0], [%1], 16;"
                 :: "r"(dst), "l"(src));
}
__device__ __forceinline__ void cp_commit() {
    asm volatile("cp.async.commit_group;");
}
template<int N> __device__ __forceinline__ void cp_wait() {
    asm volatile("cp.async.wait_group %0;" :: "n"(N));
}
__device__ __forceinline__ void ldsm4(uint32_t* r, uint32_t addr) {
    asm volatile("ldmatrix.sync.aligned.m8n8.x4.shared.b16 {%0,%1,%2,%3}, [%4];"
                 : "=r"(r[0]), "=r"(r[1]), "=r"(r[2]), "=r"(r[3]) : "r"(addr));
}
__device__ __forceinline__ void ldsm4t(uint32_t* r, uint32_t addr) {
    asm volatile("ldmatrix.sync.aligned.m8n8.x4.trans.shared.b16 {%0,%1,%2,%3}, [%4];"
                 : "=r"(r[0]), "=r"(r[1]), "=r"(r[2]), "=r"(r[3]) : "r"(addr));
}
__device__ __forceinline__ void mma16816(float* d, const uint32_t* a,
                                         const uint32_t* b) {
    asm volatile(
        "mma.sync.aligned.m16n8k16.row.col.f32.f16.f16.f32 "
        "{%0,%1,%2,%3}, {%4,%5,%6,%7}, {%8,%9}, {%0,%1,%2,%3};"
        : "+f"(d[0]), "+f"(d[1]), "+f"(d[2]), "+f"(d[3])
        : "r"(a[0]), "r"(a[1]), "r"(a[2]), "r"(a[3]), "r"(b[0]), "r"(b[1]));
}

__global__ void __launch_bounds__(256, 1) gemm_p3_mma(
    const float* __restrict__ b_out, float* __restrict__ out)
{
    extern __shared__ char dynsm[];
    const int tid  = threadIdx.x;
    const int wid  = tid >> 5;
    const int lane = tid & 31;
    const int m0 = blockIdx.x * P3_BM;
    const int n0 = blockIdx.y * P3_BN;
    const int m_w = (wid & 3) * 64;       // warp M offset
    const int n_w = (wid >> 2) * 64;      // warp N offset
    const uint32_t smb = smem_u32(dynsm);

    // per-thread load coords
    const int a_row = tid >> 2,  a_seg = tid & 3;    // + i*64 rows (4 iters)
    const int b_row = tid >> 4,  b_seg = tid & 15;   // + i*16 rows (2 iters)

    auto load_stage = [&](int chunk, int s) {
        const int kc0 = chunk * P3_BK;
        const uint32_t sa = smb + s * STAGE_BYTES;
        const uint32_t sb = sa + A_ST_BYTES;
        #pragma unroll
        for (int i = 0; i < 4; i++) {
            int row = a_row + i * 64;
            cp16(sa + (row * A_STRIDE + a_seg * 8) * 2,
                 g_a2h + (size_t)(m0 + row) * K2 + kc0 + a_seg * 8);
        }
        #pragma unroll
        for (int i = 0; i < 2; i++) {
            int row = b_row + i * 16;
            cp16(sb + (row * B_STRIDE + b_seg * 8) * 2,
                 g_b2h + (size_t)(kc0 + row) * NV + n0 + b_seg * 8);
        }
    };

    float acc[4][8][4];
    #pragma unroll
    for (int mi = 0; mi < 4; mi++)
        #pragma unroll
        for (int nj = 0; nj < 8; nj++)
            #pragma unroll
            for (int e = 0; e < 4; e++) acc[mi][nj][e] = 0.f;

    // prime stages 0..2
    #pragma unroll
    for (int c = 0; c < P3_STAGES - 1; c++) { load_stage(c, c); cp_commit(); }

    for (int c = 0; c < P3_ITERS; c++) {
        cp_wait<P3_STAGES - 2>();
        __syncthreads();
        if (c + P3_STAGES - 1 < P3_ITERS)
            load_stage(c + P3_STAGES - 1, (c + P3_STAGES - 1) % P3_STAGES);
        cp_commit();

        const int s = c % P3_STAGES;
        const uint32_t sa = smb + s * STAGE_BYTES;
        const uint32_t sb = sa + A_ST_BYTES;
        #pragma unroll
        for (int ks = 0; ks < 2; ks++) {
            uint32_t af[4][4], bf[4][4];
            #pragma unroll
            for (int mi = 0; mi < 4; mi++)
                ldsm4(af[mi], sa + ((m_w + mi * 16 + (lane & 15)) * A_STRIDE
                                    + ks * 16 + (lane >> 4) * 8) * 2);
            #pragma unroll
            for (int nj = 0; nj < 4; nj++)
                ldsm4t(bf[nj], sb + ((ks * 16 + (lane & 15)) * B_STRIDE
                                     + n_w + nj * 16 + (lane >> 4) * 8) * 2);
            #pragma unroll
            for (int mi = 0; mi < 4; mi++)
                #pragma unroll
                for (int nj = 0; nj < 4; nj++) {
                    mma16816(acc[mi][nj * 2],     af[mi], &bf[nj][0]);
                    mma16816(acc[mi][nj * 2 + 1], af[mi], &bf[nj][2]);
                }
        }
    }

    // epilogue: bias + fp32 store
    const int r_in = lane >> 2;
    const int c_in = (lane & 3) * 2;
    #pragma unroll
    for (int nj = 0; nj < 8; nj++) {
        const int col = n0 + n_w + nj * 8 + c_in;
        float2 bb = *(const float2*)&b_out[col];
        #pragma unroll
        for (int mi = 0; mi < 4; mi++) {
            const int r0 = m0 + m_w + mi * 16 + r_in;
            float2 v0 = { acc[mi][nj][0] + bb.x, acc[mi][nj][1] + bb.y };
            float2 v1 = { acc[mi][nj][2] + bb.x, acc[mi][nj][3] + bb.y };
            *(float2*)(out + (size_t)r0 * NV + col)       = v0;
            *(float2*)(out + (size_t)(r0 + 8) * NV + col) = v1;
        }
    }
}

// ---------------- phase 1 GEMM (fp32x2, unchanged) --------------------------
#define BM 128
#define BN 128
#define BK 16

__global__ void __launch_bounds__(256) gemm_p1(
    const int* __restrict__ tokens, const float* __restrict__ emb,
    const float* __restrict__ w_f, const float* __restrict__ w_i,
    const float* __restrict__ w_c, const float* __restrict__ w_o,
    const float* __restrict__ b_f, const float* __restrict__ b_i,
    const float* __restrict__ b_c, const float* __restrict__ b_o)
{
    __shared__ float As[BK][BM + 4];
    __shared__ float Bs[BK][BN];
    const int tid = threadIdx.x;
    const int m0 = blockIdx.y * BM;
    const int n0 = blockIdx.x * BN;
    const int g   = n0 >> 10;
    const int nloc = n0 & 1023;
    const float* W    = (g == 0) ? w_f : (g == 1) ? w_i : (g == 2) ? w_c : w_o;
    const float* bias = (g == 0) ? b_f : (g == 1) ? b_i : (g == 2) ? b_c : b_o;

    const int ar = tid & 127;
    const int kh = (tid >> 7) * 8;
    const float* aptr = emb + (size_t)__ldg(&tokens[m0 + ar]) * H + kh;
    const int brow0 = tid >> 5;
    const int bcol  = (tid & 31) * 4;
    const float* bptr = W + nloc + bcol;

    float4 arg0, arg1, brg0, brg1;
    arg0 = *(const float4*)(aptr + 0);
    arg1 = *(const float4*)(aptr + 4);
    brg0 = *(const float4*)(bptr + (size_t)brow0 * H);
    brg1 = *(const float4*)(bptr + (size_t)(brow0 + 8) * H);

    u64 acc[8][4];
    #pragma unroll
    for (int i = 0; i < 8; i++)
        #pragma unroll
        for (int j = 0; j < 4; j++) acc[i][j] = 0ull;

    const int ty = tid >> 4, tx = tid & 15;

    for (int kt = 0; kt < H / BK; kt++) {
        #pragma unroll
        for (int i = 0; i < 4; i++) As[kh + i][ar]     = ((float*)&arg0)[i];
        #pragma unroll
        for (int i = 0; i < 4; i++) As[kh + 4 + i][ar] = ((float*)&arg1)[i];
        *(float4*)&Bs[brow0][bcol]     = brg0;
        *(float4*)&Bs[brow0 + 8][bcol] = brg1;
        __syncthreads();
        if (kt + 1 < H / BK) {
            const float* ap = aptr + (kt + 1) * BK;
            arg0 = *(const float4*)(ap);
            arg1 = *(const float4*)(ap + 4);
            const float* bp = bptr + (size_t)((kt + 1) * BK) * H;
            brg0 = *(const float4*)(bp + (size_t)brow0 * H);
            brg1 = *(const float4*)(bp + (size_t)(brow0 + 8) * H);
        }
        #pragma unroll
        for (int k = 0; k < BK; k++) {
            float4 a0 = *(const float4*)&As[k][ty * 8];
            float4 a1 = *(const float4*)&As[k][ty * 8 + 4];
            float4 b0 = *(const float4*)&Bs[k][tx * 8];
            float4 b1 = *(const float4*)&Bs[k][tx * 8 + 4];
            u64 bp4[4] = { pk2(b0.x, b0.y), pk2(b0.z, b0.w),
                           pk2(b1.x, b1.y), pk2(b1.z, b1.w) };
            float am[8] = {a0.x, a0.y, a0.z, a0.w, a1.x, a1.y, a1.z, a1.w};
            #pragma unroll
            for (int i = 0; i < 8; i++) {
                u64 aa = pk2(am[i], am[i]);
                #pragma unroll
                for (int j = 0; j < 4; j++) fma2(acc[i][j], aa, bp4[j]);
            }
        }
        __syncthreads();
    }
    float bvv[8];
    *(float4*)&bvv[0] = *(const float4*)&bias[nloc + tx * 8];
    *(float4*)&bvv[4] = *(const float4*)&bias[nloc + tx * 8 + 4];
    #pragma unroll
    for (int i = 0; i < 8; i++) {
        float o[8];
        #pragma unroll
        for (int j = 0; j < 4; j++) upk2(o[2*j], o[2*j+1], acc[i][j]);
        #pragma unroll
        for (int jj = 0; jj < 8; jj++) o[jj] += bvv[jj];
        float* crow = g_xall + (size_t)(m0 + ty * 8 + i) * N1 + n0 + tx * 8;
        *(float4*)crow       = *(float4*)&o[0];
        *(float4*)(crow + 4) = *(float4*)&o[4];
    }
}

// ---------------- phase 2: persistent recurrent kernel (unchanged) ----------
#define REC_CTAS 128
#define REC_THREADS 256
#define SMEM_REC_FLOATS (1024*32 + 1024*16 + 8*32*16)
#define SMEM_REC_BYTES  (SMEM_REC_FLOATS * 4)

__global__ void __launch_bounds__(REC_THREADS, 1) lstm_rec(
    const float* __restrict__ u_f, const float* __restrict__ u_i,
    const float* __restrict__ u_c, const float* __restrict__ u_o)
{
    extern __shared__ float sm[];
    float* Us  = sm;
    float* hsm = sm + 1024 * 32;
    float* red = hsm + 1024 * 16;
    const int tid = threadIdx.x;
    const int cta = blockIdx.x;

    {
        const float* umat[4] = {u_f, u_i, u_c, u_o};
        for (int i = tid; i < 1024 * 32; i += REC_THREADS) {
            int k = i >> 5, cc = i & 31;
            int gg = cc >> 3, jl = cc & 7;
            Us[i] = umat[gg][(size_t)k * H + cta * 8 + jl];
        }
    }
    __syncthreads();

    const int c  = tid & 31;
    const int ks = tid >> 5;
    float creg = 0.f;
    const u64* hsm8 = (const u64*)hsm;

    for (int t = 0; t < TSTEPS; t++) {
        float pre[4];
        if (tid < 128) {
            int jloc = tid >> 4, b = tid & 15;
            size_t row = (size_t)(b * TSTEPS + t) * N1 + cta * 8 + jloc;
            #pragma unroll
            for (int gg = 0; gg < 4; gg++) pre[gg] = __ldg(&g_xall[row + gg * 1024]);
        }
        {
            const float4* gh4 = (const float4*)g_h;
            float4* h4 = (float4*)hsm;
            for (int i = tid; i < H * NB / 4; i += REC_THREADS)
                h4[i] = __ldcg(gh4 + i);
        }
        __syncthreads();

        u64 acc2[8];
        #pragma unroll
        for (int i = 0; i < 8; i++) acc2[i] = 0ull;
        {
            const int kbeg = ks * 128;
            #pragma unroll 4
            for (int k = kbeg; k < kbeg + 128; k++) {
                float u = Us[k * 32 + c];
                u64 uu = pk2(u, u);
                const u64* hp = hsm8 + (size_t)k * 8;
                #pragma unroll
                for (int i = 0; i < 8; i++) fma2(acc2[i], uu, hp[i]);
            }
        }
        {
            float* rp = red + ((ks * 32 + c) << 4);
            #pragma unroll
            for (int i = 0; i < 8; i++) upk2(rp[2*i], rp[2*i+1], acc2[i]);
        }
        __syncthreads();

        if (tid < 128) {
            int jloc = tid >> 4, b = tid & 15;
            float s[4];
            #pragma unroll
            for (int gg = 0; gg < 4; gg++) {
                int cc = gg * 8 + jloc;
                float v = 0.f;
                #pragma unroll
                for (int kk = 0; kk < 8; kk++) v += red[((kk * 32 + cc) << 4) + b];
                s[gg] = v + pre[gg];
            }
            float ft   = 1.f / (1.f + expf(-s[0]));
            float it   = 1.f / (1.f + expf(-s[1]));
            float cand = tanhf(s[2]);
            float ot   = 1.f / (1.f + expf(-s[3]));
            creg = ft * creg + it * cand;
            float hv = ot * tanhf(creg);
            int jglob = cta * 8 + jloc;
            g_h[jglob * NB + b] = hv;
            g_hs[(size_t)(b * TSTEPS + t) * H + jglob] = hv;
        }

        __syncthreads();
        if (tid == 0) {
            __threadfence();
            atomicAdd(&g_bar, 1u);
            unsigned target = (unsigned)(REC_CTAS * (t + 1));
            while (*(volatile unsigned*)&g_bar < target) __nanosleep(32);
            __threadfence();
        }
        __syncthreads();
    }
}

__global__ void init_kernel() {
    int i = blockIdx.x * blockDim.x + threadIdx.x;
    if (i == 0) g_bar = 0u;
    if (i < H * NB) g_h[i] = 0.f;
}

// ---------------- launch ----------------------------------------------------
extern "C" void kernel_launch(void* const* d_in, const int* in_sizes, int n_in,
                              void* d_out, int out_size) {
    const int*   tokens = (const int*)d_in[0];
    const float* emb    = (const float*)d_in[1];
    const float* w_f = (const float*)d_in[2];
    const float* u_f = (const float*)d_in[3];
    const float* b_f = (const float*)d_in[4];
    const float* w_i = (const float*)d_in[5];
    const float* u_i = (const float*)d_in[6];
    const float* b_i = (const float*)d_in[7];
    const float* w_c = (const float*)d_in[8];
    const float* u_c = (const float*)d_in[9];
    const float* b_c = (const float*)d_in[10];
    const float* w_o = (const float*)d_in[11];
    const float* u_o = (const float*)d_in[12];
    const float* b_o = (const float*)d_in[13];
    const float* w_out = (const float*)d_in[14];
    const float* b_out = (const float*)d_in[15];
    float* out = (float*)d_out;

    cudaFuncSetAttribute(lstm_rec, cudaFuncAttributeMaxDynamicSharedMemorySize,
                         SMEM_REC_BYTES);
    cudaFuncSetAttribute(gemm_p3_mma, cudaFuncAttributeMaxDynamicSharedMemorySize,
                         P3_SMEM);

    init_kernel<<<64, 256>>>();
    conv_w2<<<(int)(((size_t)H * NV + 255) / 256), 256>>>(w_out);
    gemm_p1<<<dim3(N1 / BN, BT / BM), 256>>>(tokens, emb, w_f, w_i, w_c, w_o,
                                             b_f, b_i, b_c, b_o);
    lstm_rec<<<REC_CTAS, REC_THREADS, SMEM_REC_BYTES>>>(u_f, u_i, u_c, u_o);
    conv_a2<<<(int)(((size_t)BT * H + 255) / 256), 256>>>();
    gemm_p3_mma<<<dim3(BT / P3_BM, NV / P3_BN), 256, P3_SMEM>>>(b_out, out);
}

// round 6
// speedup vs baseline: 1.8829x; 1.0741x over previous
#include <cuda_runtime.h>
#include <cuda_fp16.h>
#include <cstdint>

#define H   1024
#define NB  16
#define TSTEPS 256
#define BT  4096      // B*T
#define N1  4096      // 4*H
#define NV  32000
#define K2  2048      // [Ah | Al] split-K

typedef unsigned long long u64;

// ---------------- scratch (device globals; no allocations allowed) ----------
__device__ float g_xall[(size_t)BT * N1];       // gate pre-activations (64 MB)
__device__ float g_hs[(size_t)BT * H];          // hidden states fp32 (16 MB)
__device__ float g_h[H * NB];                   // current h [k][b]
__device__ unsigned g_bar;                      // grid barrier
__device__ __half g_a2h[(size_t)BT * K2];       // [m][Ah|Al] fp16 (16.8 MB)
__device__ __half g_b2h[(size_t)K2 * NV];       // [Bh;Bh] fp16 (131 MB)

// ---------------- packed f32x2 helpers --------------------------------------
__device__ __forceinline__ u64 pk2(float lo, float hi) {
    u64 r; asm("mov.b64 %0, {%1,%2};" : "=l"(r) : "f"(lo), "f"(hi)); return r;
}
__device__ __forceinline__ void fma2(u64 &d, u64 a, u64 b) {
    asm("fma.rn.f32x2 %0, %1, %2, %0;" : "+l"(d) : "l"(a), "l"(b));
}
__device__ __forceinline__ void upk2(float &lo, float &hi, u64 v) {
    asm("mov.b64 {%0,%1}, %2;" : "=f"(lo), "=f"(hi) : "l"(v));
}

__device__ __forceinline__ uint32_t smem_u32(const void* p) {
    uint32_t a;
    asm("{ .reg .u64 t; cvta.to.shared.u64 t, %1; cvt.u32.u64 %0, t; }"
        : "=r"(a) : "l"(p));
    return a;
}

// ---------------- cp.async helpers ------------------------------------------
__device__ __forceinline__ void cp16(uint32_t dst, const void* src) {
    asm volatile("cp.async.cg.shared.global [%0], [%1], 16;"
                 :: "r"(dst), "l"(src));
}
__device__ __forceinline__ void cp_commit() {
    asm volatile("cp.async.commit_group;");
}
template<int N> __device__ __forceinline__ void cp_wait() {
    asm volatile("cp.async.wait_group %0;" :: "n"(N));
}

// ---------------- conversion kernels ----------------------------------------
__global__ void conv_w2(const float* __restrict__ w) {
    size_t idx = (size_t)blockIdx.x * blockDim.x + threadIdx.x;
    if (idx >= (size_t)H * NV) return;
    __half hv = __float2half(w[idx]);
    g_b2h[idx] = hv;                       // rows 0..1023: Bh (for Ah)
    g_b2h[idx + (size_t)H * NV] = hv;      // rows 1024..2047: Bh (for Al)
}

__global__ void conv_a2() {
    size_t idx = (size_t)blockIdx.x * blockDim.x + threadIdx.x;
    if (idx >= (size_t)BT * H) return;
    size_t m = idx >> 10, k = idx & 1023;
    float x = g_hs[idx];
    __half hi = __float2half(x);
    __half lo = __float2half(x - __half2float(hi));
    __half* row = g_a2h + m * K2;
    row[k] = hi; row[k + 1024] = lo;
}

// ---------------- phase 3: mma.sync fp16 GEMM 256x128x32, 4-stage cp.async --
#define P3_BM 256
#define P3_BN 128
#define P3_BK 32
#define P3_STAGES 4
#define A_STRIDE 40                       // halves (80 B, pad 32->40)
#define B_STRIDE 136                      // halves (272 B, pad 128->136)
#define A_ST_BYTES (P3_BM * A_STRIDE * 2) // 20480
#define B_ST_BYTES (P3_BK * B_STRIDE * 2) // 8704
#define STAGE_BYTES (A_ST_BYTES + B_ST_BYTES)
#define P3_SMEM (P3_STAGES * STAGE_BYTES) // 116736
#define P3_ITERS (K2 / P3_BK)             // 64

__device__ __forceinline__ void ldsm4(uint32_t* r, uint32_t addr) {
    asm volatile("ldmatrix.sync.aligned.m8n8.x4.shared.b16 {%0,%1,%2,%3}, [%4];"
                 : "=r"(r[0]), "=r"(r[1]), "=r"(r[2]), "=r"(r[3]) : "r"(addr));
}
__device__ __forceinline__ void ldsm4t(uint32_t* r, uint32_t addr) {
    asm volatile("ldmatrix.sync.aligned.m8n8.x4.trans.shared.b16 {%0,%1,%2,%3}, [%4];"
                 : "=r"(r[0]), "=r"(r[1]), "=r"(r[2]), "=r"(r[3]) : "r"(addr));
}
__device__ __forceinline__ void mma16816(float* d, const uint32_t* a,
                                         const uint32_t* b) {
    asm volatile(
        "mma.sync.aligned.m16n8k16.row.col.f32.f16.f16.f32 "
        "{%0,%1,%2,%3}, {%4,%5,%6,%7}, {%8,%9}, {%0,%1,%2,%3};"
        : "+f"(d[0]), "+f"(d[1]), "+f"(d[2]), "+f"(d[3])
        : "r"(a[0]), "r"(a[1]), "r"(a[2]), "r"(a[3]), "r"(b[0]), "r"(b[1]));
}

__global__ void __launch_bounds__(256, 1) gemm_p3_mma(
    const float* __restrict__ b_out, float* __restrict__ out)
{
    extern __shared__ char dynsm[];
    const int tid  = threadIdx.x;
    const int wid  = tid >> 5;
    const int lane = tid & 31;
    const int m0 = blockIdx.x * P3_BM;
    const int n0 = blockIdx.y * P3_BN;
    const int m_w = (wid & 3) * 64;       // warp M offset
    const int n_w = (wid >> 2) * 64;      // warp N offset
    const uint32_t smb = smem_u32(dynsm);

    // per-thread load coords
    const int a_row = tid >> 2,  a_seg = tid & 3;    // + i*64 rows (4 iters)
    const int b_row = tid >> 4,  b_seg = tid & 15;   // + i*16 rows (2 iters)

    auto load_stage = [&](int chunk, int s) {
        const int kc0 = chunk * P3_BK;
        const uint32_t sa = smb + s * STAGE_BYTES;
        const uint32_t sb = sa + A_ST_BYTES;
        #pragma unroll
        for (int i = 0; i < 4; i++) {
            int row = a_row + i * 64;
            cp16(sa + (row * A_STRIDE + a_seg * 8) * 2,
                 g_a2h + (size_t)(m0 + row) * K2 + kc0 + a_seg * 8);
        }
        #pragma unroll
        for (int i = 0; i < 2; i++) {
            int row = b_row + i * 16;
            cp16(sb + (row * B_STRIDE + b_seg * 8) * 2,
                 g_b2h + (size_t)(kc0 + row) * NV + n0 + b_seg * 8);
        }
    };

    float acc[4][8][4];
    #pragma unroll
    for (int mi = 0; mi < 4; mi++)
        #pragma unroll
        for (int nj = 0; nj < 8; nj++)
            #pragma unroll
            for (int e = 0; e < 4; e++) acc[mi][nj][e] = 0.f;

    // prime stages 0..2
    #pragma unroll
    for (int c = 0; c < P3_STAGES - 1; c++) { load_stage(c, c); cp_commit(); }

    for (int c = 0; c < P3_ITERS; c++) {
        cp_wait<P3_STAGES - 2>();
        __syncthreads();
        if (c + P3_STAGES - 1 < P3_ITERS)
            load_stage(c + P3_STAGES - 1, (c + P3_STAGES - 1) % P3_STAGES);
        cp_commit();

        const int s = c % P3_STAGES;
        const uint32_t sa = smb + s * STAGE_BYTES;
        const uint32_t sb = sa + A_ST_BYTES;
        #pragma unroll
        for (int ks = 0; ks < 2; ks++) {
            uint32_t af[4][4], bf[4][4];
            #pragma unroll
            for (int mi = 0; mi < 4; mi++)
                ldsm4(af[mi], sa + ((m_w + mi * 16 + (lane & 15)) * A_STRIDE
                                    + ks * 16 + (lane >> 4) * 8) * 2);
            #pragma unroll
            for (int nj = 0; nj < 4; nj++)
                ldsm4t(bf[nj], sb + ((ks * 16 + (lane & 15)) * B_STRIDE
                                     + n_w + nj * 16 + (lane >> 4) * 8) * 2);
            #pragma unroll
            for (int mi = 0; mi < 4; mi++)
                #pragma unroll
                for (int nj = 0; nj < 4; nj++) {
                    mma16816(acc[mi][nj * 2],     af[mi], &bf[nj][0]);
                    mma16816(acc[mi][nj * 2 + 1], af[mi], &bf[nj][2]);
                }
        }
    }

    // epilogue: bias + fp32 store
    const int r_in = lane >> 2;
    const int c_in = (lane & 3) * 2;
    #pragma unroll
    for (int nj = 0; nj < 8; nj++) {
        const int col = n0 + n_w + nj * 8 + c_in;
        float2 bb = *(const float2*)&b_out[col];
        #pragma unroll
        for (int mi = 0; mi < 4; mi++) {
            const int r0 = m0 + m_w + mi * 16 + r_in;
            float2 v0 = { acc[mi][nj][0] + bb.x, acc[mi][nj][1] + bb.y };
            float2 v1 = { acc[mi][nj][2] + bb.x, acc[mi][nj][3] + bb.y };
            *(float2*)(out + (size_t)r0 * NV + col)       = v0;
            *(float2*)(out + (size_t)(r0 + 8) * NV + col) = v1;
        }
    }
}

// ---------------- phase 1 GEMM (fp32x2, unchanged) --------------------------
#define BM 128
#define BN 128
#define BK 16

__global__ void __launch_bounds__(256) gemm_p1(
    const int* __restrict__ tokens, const float* __restrict__ emb,
    const float* __restrict__ w_f, const float* __restrict__ w_i,
    const float* __restrict__ w_c, const float* __restrict__ w_o,
    const float* __restrict__ b_f, const float* __restrict__ b_i,
    const float* __restrict__ b_c, const float* __restrict__ b_o)
{
    __shared__ float As[BK][BM + 4];
    __shared__ float Bs[BK][BN];
    const int tid = threadIdx.x;
    const int m0 = blockIdx.y * BM;
    const int n0 = blockIdx.x * BN;
    const int g   = n0 >> 10;
    const int nloc = n0 & 1023;
    const float* W    = (g == 0) ? w_f : (g == 1) ? w_i : (g == 2) ? w_c : w_o;
    const float* bias = (g == 0) ? b_f : (g == 1) ? b_i : (g == 2) ? b_c : b_o;

    const int ar = tid & 127;
    const int kh = (tid >> 7) * 8;
    const float* aptr = emb + (size_t)__ldg(&tokens[m0 + ar]) * H + kh;
    const int brow0 = tid >> 5;
    const int bcol  = (tid & 31) * 4;
    const float* bptr = W + nloc + bcol;

    float4 arg0, arg1, brg0, brg1;
    arg0 = *(const float4*)(aptr + 0);
    arg1 = *(const float4*)(aptr + 4);
    brg0 = *(const float4*)(bptr + (size_t)brow0 * H);
    brg1 = *(const float4*)(bptr + (size_t)(brow0 + 8) * H);

    u64 acc[8][4];
    #pragma unroll
    for (int i = 0; i < 8; i++)
        #pragma unroll
        for (int j = 0; j < 4; j++) acc[i][j] = 0ull;

    const int ty = tid >> 4, tx = tid & 15;

    for (int kt = 0; kt < H / BK; kt++) {
        #pragma unroll
        for (int i = 0; i < 4; i++) As[kh + i][ar]     = ((float*)&arg0)[i];
        #pragma unroll
        for (int i = 0; i < 4; i++) As[kh + 4 + i][ar] = ((float*)&arg1)[i];
        *(float4*)&Bs[brow0][bcol]     = brg0;
        *(float4*)&Bs[brow0 + 8][bcol] = brg1;
        __syncthreads();
        if (kt + 1 < H / BK) {
            const float* ap = aptr + (kt + 1) * BK;
            arg0 = *(const float4*)(ap);
            arg1 = *(const float4*)(ap + 4);
            const float* bp = bptr + (size_t)((kt + 1) * BK) * H;
            brg0 = *(const float4*)(bp + (size_t)brow0 * H);
            brg1 = *(const float4*)(bp + (size_t)(brow0 + 8) * H);
        }
        #pragma unroll
        for (int k = 0; k < BK; k++) {
            float4 a0 = *(const float4*)&As[k][ty * 8];
            float4 a1 = *(const float4*)&As[k][ty * 8 + 4];
            float4 b0 = *(const float4*)&Bs[k][tx * 8];
            float4 b1 = *(const float4*)&Bs[k][tx * 8 + 4];
            u64 bp4[4] = { pk2(b0.x, b0.y), pk2(b0.z, b0.w),
                           pk2(b1.x, b1.y), pk2(b1.z, b1.w) };
            float am[8] = {a0.x, a0.y, a0.z, a0.w, a1.x, a1.y, a1.z, a1.w};
            #pragma unroll
            for (int i = 0; i < 8; i++) {
                u64 aa = pk2(am[i], am[i]);
                #pragma unroll
                for (int j = 0; j < 4; j++) fma2(acc[i][j], aa, bp4[j]);
            }
        }
        __syncthreads();
    }
    float bvv[8];
    *(float4*)&bvv[0] = *(const float4*)&bias[nloc + tx * 8];
    *(float4*)&bvv[4] = *(const float4*)&bias[nloc + tx * 8 + 4];
    #pragma unroll
    for (int i = 0; i < 8; i++) {
        float o[8];
        #pragma unroll
        for (int j = 0; j < 4; j++) upk2(o[2*j], o[2*j+1], acc[i][j]);
        #pragma unroll
        for (int jj = 0; jj < 8; jj++) o[jj] += bvv[jj];
        float* crow = g_xall + (size_t)(m0 + ty * 8 + i) * N1 + n0 + tx * 8;
        *(float4*)crow       = *(float4*)&o[0];
        *(float4*)(crow + 4) = *(float4*)&o[4];
    }
}

// ---------------- phase 2: persistent recurrent kernel (rewritten) ----------
// SMEM layout (floats):
//   Us2 [k4=256][c=32][4]  : 32768 floats (128 KB)  transposed-U, float4 per 4k
//   hsm [k=1024][b=16]     : 16384 floats (64 KB)
//   red [ks=8][c=32][b=16] :  4096 floats (16 KB)
#define REC_CTAS 128
#define REC_THREADS 256
#define US_FLOATS  32768
#define HS_FLOATS  16384
#define RED_FLOATS 4096
#define SMEM_REC_BYTES ((US_FLOATS + HS_FLOATS + RED_FLOATS) * 4)

__global__ void __launch_bounds__(REC_THREADS, 1) lstm_rec(
    const float* __restrict__ u_f, const float* __restrict__ u_i,
    const float* __restrict__ u_c, const float* __restrict__ u_o)
{
    extern __shared__ float sm[];
    float* Us2 = sm;
    float* hsm = sm + US_FLOATS;
    float* red = sm + US_FLOATS + HS_FLOATS;
    const int tid  = threadIdx.x;
    const int lane = tid & 31;
    const int wid  = tid >> 5;       // warp == k-slice (8 slices of 128 k)
    const int cta  = blockIdx.x;

    // load + transpose this CTA's U slice: Us2[k4][c][j] = U_g[k4*4+j][cta*8+jl]
    {
        const float* umat[4] = {u_f, u_i, u_c, u_o};
        for (int i = tid; i < US_FLOATS; i += REC_THREADS) {
            int k = i >> 5, cc = i & 31;          // iterate (k, c)
            int gg = cc >> 3, jl = cc & 7;
            int k4 = k >> 2, j = k & 3;
            Us2[k4 * 128 + cc * 4 + j] = umat[gg][(size_t)k * H + cta * 8 + jl];
        }
    }
    __syncthreads();

    const int c2 = lane & 15;        // column pair
    const int bh = lane >> 4;        // batch half (8 batches)
    const int c0 = c2 * 2, c1 = c0 + 1;
    const int ks = wid;
    const uint32_t hsm_a = smem_u32(hsm);
    const float4* Us4 = (const float4*)Us2;   // [k4*32 + c]
    const float4* h4  = (const float4*)hsm;   // [k*4 + q]
    float creg = 0.f;                // cell state (tid < 128)

    // prefetch pre-activations for t=0
    float pre[4];
    int jloc_u = tid >> 4, b_u = tid & 15;    // update-phase coords
    if (tid < 128) {
        size_t row = (size_t)(b_u * TSTEPS + 0) * N1 + cta * 8 + jloc_u;
        #pragma unroll
        for (int gg = 0; gg < 4; gg++) pre[gg] = __ldg(&g_xall[row + gg * 1024]);
    }

    for (int t = 0; t < TSTEPS; t++) {
        // stage h via cp.async (L1-bypassing, 16 x 16B per thread)
        {
            const float* src = g_h + tid * 4;
            uint32_t dst = hsm_a + tid * 16;
            #pragma unroll
            for (int i = 0; i < 16; i++)
                cp16(dst + i * 4096, src + i * 1024);
            cp_commit();
        }
        cp_wait<0>();
        __syncthreads();

        // inner product: thread owns 2 cols x 8 batches over its 128-k slice
        u64 acc[8];
        #pragma unroll
        for (int i = 0; i < 8; i++) acc[i] = 0ull;
        {
            const int k4beg = ks * 32;
            #pragma unroll 4
            for (int k4 = k4beg; k4 < k4beg + 32; k4++) {
                float4 u0 = Us4[k4 * 32 + c0];
                float4 u1 = Us4[k4 * 32 + c1];
                #pragma unroll
                for (int j = 0; j < 4; j++) {
                    int k = k4 * 4 + j;
                    float4 ha = h4[k * 4 + bh * 2];
                    float4 hb = h4[k * 4 + bh * 2 + 1];
                    u64 p0 = pk2(ha.x, ha.y), p1 = pk2(ha.z, ha.w);
                    u64 p2 = pk2(hb.x, hb.y), p3 = pk2(hb.z, hb.w);
                    float uj0 = ((const float*)&u0)[j];
                    float uj1 = ((const float*)&u1)[j];
                    u64 w0 = pk2(uj0, uj0), w1 = pk2(uj1, uj1);
                    fma2(acc[0], w0, p0); fma2(acc[1], w0, p1);
                    fma2(acc[2], w0, p2); fma2(acc[3], w0, p3);
                    fma2(acc[4], w1, p0); fma2(acc[5], w1, p1);
                    fma2(acc[6], w1, p2); fma2(acc[7], w1, p3);
                }
            }
        }
        // store partials: red[ks][c][b], b-half bh
        {
            float o[16];
            #pragma unroll
            for (int i = 0; i < 8; i++) upk2(o[2*i], o[2*i+1], acc[i]);
            float* r0 = red + (ks * 32 + c0) * 16 + bh * 8;
            float* r1 = red + (ks * 32 + c1) * 16 + bh * 8;
            *(float4*)(r0)     = *(float4*)&o[0];
            *(float4*)(r0 + 4) = *(float4*)&o[4];
            *(float4*)(r1)     = *(float4*)&o[8];
            *(float4*)(r1 + 4) = *(float4*)&o[12];
        }
        __syncthreads();

        // reduce k-slices + nonlinearity + state update (128 threads)
        if (tid < 128) {
            float s[4];
            #pragma unroll
            for (int gg = 0; gg < 4; gg++) {
                int cc = gg * 8 + jloc_u;
                float v = 0.f;
                #pragma unroll
                for (int kk = 0; kk < 8; kk++) v += red[(kk * 32 + cc) * 16 + b_u];
                s[gg] = v + pre[gg];
            }
            float ft   = 1.f / (1.f + expf(-s[0]));
            float it   = 1.f / (1.f + expf(-s[1]));
            float cand = tanhf(s[2]);
            float ot   = 1.f / (1.f + expf(-s[3]));
            creg = ft * creg + it * cand;
            float hv = ot * tanhf(creg);
            int jglob = cta * 8 + jloc_u;
            g_h[jglob * NB + b_u] = hv;
            g_hs[(size_t)(b_u * TSTEPS + t) * H + jglob] = hv;
        }

        // prefetch next step's pre-activations (overlaps barrier wait)
        if (tid < 128 && t + 1 < TSTEPS) {
            size_t row = (size_t)(b_u * TSTEPS + t + 1) * N1 + cta * 8 + jloc_u;
            #pragma unroll
            for (int gg = 0; gg < 4; gg++) pre[gg] = __ldg(&g_xall[row + gg * 1024]);
        }

        // grid barrier (monotonic counter)
        __syncthreads();
        if (tid == 0) {
            __threadfence();
            atomicAdd(&g_bar, 1u);
            const unsigned target = (unsigned)(REC_CTAS * (t + 1));
            int spins = 0;
            while (true) {
                unsigned v;
                asm volatile("ld.global.cg.u32 %0, [%1];" : "=r"(v) : "l"(&g_bar));
                if (v >= target) break;
                if (++spins > 8) __nanosleep(32);
            }
            __threadfence();
        }
        __syncthreads();
    }
}

__global__ void init_kernel() {
    int i = blockIdx.x * blockDim.x + threadIdx.x;
    if (i == 0) g_bar = 0u;
    if (i < H * NB) g_h[i] = 0.f;
}

// ---------------- launch ----------------------------------------------------
extern "C" void kernel_launch(void* const* d_in, const int* in_sizes, int n_in,
                              void* d_out, int out_size) {
    const int*   tokens = (const int*)d_in[0];
    const float* emb    = (const float*)d_in[1];
    const float* w_f = (const float*)d_in[2];
    const float* u_f = (const float*)d_in[3];
    const float* b_f = (const float*)d_in[4];
    const float* w_i = (const float*)d_in[5];
    const float* u_i = (const float*)d_in[6];
    const float* b_i = (const float*)d_in[7];
    const float* w_c = (const float*)d_in[8];
    const float* u_c = (const float*)d_in[9];
    const float* b_c = (const float*)d_in[10];
    const float* w_o = (const float*)d_in[11];
    const float* u_o = (const float*)d_in[12];
    const float* b_o = (const float*)d_in[13];
    const float* w_out = (const float*)d_in[14];
    const float* b_out = (const float*)d_in[15];
    float* out = (float*)d_out;

    cudaFuncSetAttribute(lstm_rec, cudaFuncAttributeMaxDynamicSharedMemorySize,
                         SMEM_REC_BYTES);
    cudaFuncSetAttribute(gemm_p3_mma, cudaFuncAttributeMaxDynamicSharedMemorySize,
                         P3_SMEM);

    init_kernel<<<64, 256>>>();
    conv_w2<<<(int)(((size_t)H * NV + 255) / 256), 256>>>(w_out);
    gemm_p1<<<dim3(N1 / BN, BT / BM), 256>>>(tokens, emb, w_f, w_i, w_c, w_o,
                                             b_f, b_i, b_c, b_o);
    lstm_rec<<<REC_CTAS, REC_THREADS, SMEM_REC_BYTES>>>(u_f, u_i, u_c, u_o);
    conv_a2<<<(int)(((size_t)BT * H + 255) / 256), 256>>>();
    gemm_p3_mma<<<dim3(BT / P3_BM, NV / P3_BN), 256, P3_SMEM>>>(b_out, out);
}

// round 7
// speedup vs baseline: 2.2775x; 1.2096x over previous
#include <cuda_runtime.h>
#include <cuda_fp16.h>
#include <cstdint>

#define H   1024
#define NB  16
#define TSTEPS 256
#define BT  4096      // B*T
#define N1  4096      // 4*H
#define NV  32000
#define K2  2048      // p3: [Ah | Al] split-K
#define K1  3072      // p1: [xh | xl | xh] split-K

typedef unsigned long long u64;

// ---------------- scratch (device globals; no allocations allowed) ----------
__device__ float g_xall[(size_t)BT * N1];       // gate pre-activations (64 MB)
__device__ float g_hs[(size_t)BT * H];          // hidden states fp32 (16 MB)
__device__ float g_h[H * NB];                   // current h [k][b]
__device__ unsigned g_bar;                      // grid barrier
__device__ __half g_a2h[(size_t)BT * K2];       // p3 A: [m][Ah|Al] (16.8 MB)
__device__ __half g_b2h[(size_t)K2 * NV];       // p3 B: [Bh;Bh] (131 MB)
__device__ __half g_a1h[(size_t)BT * K1];       // p1 A: [m][xh|xl|xh] (25 MB)
__device__ __half g_b1h[(size_t)K1 * N1];       // p1 B: [Wh;Wh;Wl] (25 MB)
__device__ float  g_bias1[N1];                  // concat gate biases

// ---------------- packed f32x2 helpers --------------------------------------
__device__ __forceinline__ u64 pk2(float lo, float hi) {
    u64 r; asm("mov.b64 %0, {%1,%2};" : "=l"(r) : "f"(lo), "f"(hi)); return r;
}
__device__ __forceinline__ void fma2(u64 &d, u64 a, u64 b) {
    asm("fma.rn.f32x2 %0, %1, %2, %0;" : "+l"(d) : "l"(a), "l"(b));
}
__device__ __forceinline__ void upk2(float &lo, float &hi, u64 v) {
    asm("mov.b64 {%0,%1}, %2;" : "=f"(lo), "=f"(hi) : "l"(v));
}
__device__ __forceinline__ uint32_t smem_u32(const void* p) {
    uint32_t a;
    asm("{ .reg .u64 t; cvta.to.shared.u64 t, %1; cvt.u32.u64 %0, t; }"
        : "=r"(a) : "l"(p));
    return a;
}

// ---------------- cp.async helpers ------------------------------------------
__device__ __forceinline__ void cp16(uint32_t dst, const void* src) {
    asm volatile("cp.async.cg.shared.global [%0], [%1], 16;"
                 :: "r"(dst), "l"(src));
}
__device__ __forceinline__ void cp_commit() {
    asm volatile("cp.async.commit_group;");
}
template<int N> __device__ __forceinline__ void cp_wait() {
    asm volatile("cp.async.wait_group %0;" :: "n"(N));
}

// ---------------- mma helpers ------------------------------------------------
__device__ __forceinline__ void ldsm4(uint32_t* r, uint32_t addr) {
    asm volatile("ldmatrix.sync.aligned.m8n8.x4.shared.b16 {%0,%1,%2,%3}, [%4];"
                 : "=r"(r[0]), "=r"(r[1]), "=r"(r[2]), "=r"(r[3]) : "r"(addr));
}
__device__ __forceinline__ void ldsm4t(uint32_t* r, uint32_t addr) {
    asm volatile("ldmatrix.sync.aligned.m8n8.x4.trans.shared.b16 {%0,%1,%2,%3}, [%4];"
                 : "=r"(r[0]), "=r"(r[1]), "=r"(r[2]), "=r"(r[3]) : "r"(addr));
}
__device__ __forceinline__ void mma16816(float* d, const uint32_t* a,
                                         const uint32_t* b) {
    asm volatile(
        "mma.sync.aligned.m16n8k16.row.col.f32.f16.f16.f32 "
        "{%0,%1,%2,%3}, {%4,%5,%6,%7}, {%8,%9}, {%0,%1,%2,%3};"
        : "+f"(d[0]), "+f"(d[1]), "+f"(d[2]), "+f"(d[3])
        : "r"(a[0]), "r"(a[1]), "r"(a[2]), "r"(a[3]), "r"(b[0]), "r"(b[1]));
}

// ---------------- conversion kernels ----------------------------------------
__global__ void conv_w2(const float* __restrict__ w) {
    size_t idx = (size_t)blockIdx.x * blockDim.x + threadIdx.x;
    if (idx >= (size_t)H * NV) return;
    __half hv = __float2half(w[idx]);
    g_b2h[idx] = hv;
    g_b2h[idx + (size_t)H * NV] = hv;
}

__global__ void conv_a2() {
    size_t idx = (size_t)blockIdx.x * blockDim.x + threadIdx.x;
    if (idx >= (size_t)BT * H) return;
    size_t m = idx >> 10, k = idx & 1023;
    float x = g_hs[idx];
    __half hi = __float2half(x);
    __half lo = __float2half(x - __half2float(hi));
    __half* row = g_a2h + m * K2;
    row[k] = hi; row[k + 1024] = lo;
}

// p1 B: [Wh;Wh;Wl] over concatenated gate columns; also bias concat
__global__ void conv_w1(const float* __restrict__ wf, const float* __restrict__ wi,
                        const float* __restrict__ wc, const float* __restrict__ wo,
                        const float* __restrict__ bf_, const float* __restrict__ bi_,
                        const float* __restrict__ bc_, const float* __restrict__ bo_) {
    size_t idx = (size_t)blockIdx.x * blockDim.x + threadIdx.x;
    if (idx < N1) {
        int g = (int)(idx >> 10), j = (int)(idx & 1023);
        const float* bs = (g == 0) ? bf_ : (g == 1) ? bi_ : (g == 2) ? bc_ : bo_;
        g_bias1[idx] = bs[j];
    }
    if (idx >= (size_t)H * N1) return;
    int k = (int)(idx >> 12);
    int col = (int)(idx & 4095);
    int g = col >> 10, j = col & 1023;
    const float* w = (g == 0) ? wf : (g == 1) ? wi : (g == 2) ? wc : wo;
    float x = w[(size_t)k * H + j];
    __half hi = __float2half(x);
    __half lo = __float2half(x - __half2float(hi));
    g_b1h[(size_t)k * N1 + col] = hi;
    g_b1h[(size_t)(k + 1024) * N1 + col] = hi;
    g_b1h[(size_t)(k + 2048) * N1 + col] = lo;
}

// p1 A: gather embedding + hi/lo split -> [xh|xl|xh]
__global__ void conv_x(const int* __restrict__ tokens, const float* __restrict__ emb) {
    size_t idx = (size_t)blockIdx.x * blockDim.x + threadIdx.x;
    if (idx >= (size_t)BT * H) return;
    size_t m = idx >> 10, k = idx & 1023;
    int tok = __ldg(&tokens[m]);
    float x = __ldg(&emb[(size_t)tok * H + k]);
    __half hi = __float2half(x);
    __half lo = __float2half(x - __half2float(hi));
    __half* row = g_a1h + m * K1;
    row[k] = hi; row[k + 1024] = lo; row[k + 2048] = hi;
}

// ---------------- generic mma GEMM: 128x128x32 tile, 4-stage, 2 CTA/SM ------
// MODE 0: p1  A=g_a1h (lda K1), B=g_b1h (ldb N1), bias=g_bias1, C=g_xall
// MODE 1: p3  A=g_a2h (lda K2), B=g_b2h (ldb NV), bias=arg, C=arg
#define GM_BM 128
#define GM_BK 32
#define GM_STAGES 4
#define GA_STRIDE 40                       // halves (80 B)
#define GB_STRIDE 136                      // halves (272 B)
#define GA_ST_BYTES (GM_BM * GA_STRIDE * 2)   // 10240
#define GB_ST_BYTES (GM_BK * GB_STRIDE * 2)   // 8704
#define GM_STAGE_BYTES (GA_ST_BYTES + GB_ST_BYTES)
#define GM_SMEM (GM_STAGES * GM_STAGE_BYTES)  // 75776

template<int MODE>
__global__ void __launch_bounds__(256, 2) gemm_mma(
    const float* __restrict__ bias_g, float* __restrict__ outg)
{
    constexpr int lda = MODE ? K2 : K1;
    constexpr int ldb = MODE ? NV : N1;
    constexpr int ldc = MODE ? NV : N1;
    constexpr int kiters = (MODE ? K2 : K1) / GM_BK;
    const __half* A = MODE ? g_a2h : g_a1h;
    const __half* B = MODE ? g_b2h : g_b1h;
    const float* bias = MODE ? bias_g : g_bias1;
    float* C = MODE ? outg : g_xall;

    extern __shared__ char dynsm[];
    const int tid  = threadIdx.x;
    const int wid  = tid >> 5;
    const int lane = tid & 31;
    const int m0 = blockIdx.x * GM_BM;
    const int n0 = blockIdx.y * 128;
    const int m_w = (wid & 3) * 32;       // warp M offset
    const int n_w = (wid >> 2) * 64;      // warp N offset
    const uint32_t smb = smem_u32(dynsm);

    const int a_row = tid >> 2,  a_seg = tid & 3;    // rows +0,+64
    const int b_row = tid >> 4,  b_seg = tid & 15;   // rows +0,+16

    auto load_stage = [&](int chunk, int s) {
        const int kc0 = chunk * GM_BK;
        const uint32_t sa = smb + s * GM_STAGE_BYTES;
        const uint32_t sb = sa + GA_ST_BYTES;
        #pragma unroll
        for (int i = 0; i < 2; i++) {
            int row = a_row + i * 64;
            cp16(sa + (row * GA_STRIDE + a_seg * 8) * 2,
                 A + (size_t)(m0 + row) * lda + kc0 + a_seg * 8);
        }
        #pragma unroll
        for (int i = 0; i < 2; i++) {
            int row = b_row + i * 16;
            cp16(sb + (row * GB_STRIDE + b_seg * 8) * 2,
                 B + (size_t)(kc0 + row) * ldb + n0 + b_seg * 8);
        }
    };

    float acc[2][8][4];
    #pragma unroll
    for (int mi = 0; mi < 2; mi++)
        #pragma unroll
        for (int nj = 0; nj < 8; nj++)
            #pragma unroll
            for (int e = 0; e < 4; e++) acc[mi][nj][e] = 0.f;

    #pragma unroll
    for (int c = 0; c < GM_STAGES - 1; c++) { load_stage(c, c); cp_commit(); }

    for (int c = 0; c < kiters; c++) {
        cp_wait<GM_STAGES - 2>();
        __syncthreads();
        if (c + GM_STAGES - 1 < kiters)
            load_stage(c + GM_STAGES - 1, (c + GM_STAGES - 1) % GM_STAGES);
        cp_commit();

        const int s = c % GM_STAGES;
        const uint32_t sa = smb + s * GM_STAGE_BYTES;
        const uint32_t sb = sa + GA_ST_BYTES;
        #pragma unroll
        for (int ks = 0; ks < 2; ks++) {
            uint32_t af[2][4], bf[4][4];
            #pragma unroll
            for (int mi = 0; mi < 2; mi++)
                ldsm4(af[mi], sa + ((m_w + mi * 16 + (lane & 15)) * GA_STRIDE
                                    + ks * 16 + (lane >> 4) * 8) * 2);
            #pragma unroll
            for (int nj = 0; nj < 4; nj++)
                ldsm4t(bf[nj], sb + ((ks * 16 + (lane & 15)) * GB_STRIDE
                                     + n_w + nj * 16 + (lane >> 4) * 8) * 2);
            #pragma unroll
            for (int mi = 0; mi < 2; mi++)
                #pragma unroll
                for (int nj = 0; nj < 4; nj++) {
                    mma16816(acc[mi][nj * 2],     af[mi], &bf[nj][0]);
                    mma16816(acc[mi][nj * 2 + 1], af[mi], &bf[nj][2]);
                }
        }
    }

    // epilogue: bias + fp32 store
    const int r_in = lane >> 2;
    const int c_in = (lane & 3) * 2;
    #pragma unroll
    for (int nj = 0; nj < 8; nj++) {
        const int col = n0 + n_w + nj * 8 + c_in;
        float2 bb = *(const float2*)&bias[col];
        #pragma unroll
        for (int mi = 0; mi < 2; mi++) {
            const int r0 = m0 + m_w + mi * 16 + r_in;
            float2 v0 = { acc[mi][nj][0] + bb.x, acc[mi][nj][1] + bb.y };
            float2 v1 = { acc[mi][nj][2] + bb.x, acc[mi][nj][3] + bb.y };
            *(float2*)(C + (size_t)r0 * ldc + col)       = v0;
            *(float2*)(C + (size_t)(r0 + 8) * ldc + col) = v1;
        }
    }
}

// ---------------- phase 2: persistent recurrent kernel ----------------------
// SMEM (floats): Us2 [k4=256][c=32][4] 128KB | hsm [k][b] 64KB | red 16KB
#define REC_CTAS 128
#define REC_THREADS 256
#define US_FLOATS  32768
#define HS_FLOATS  16384
#define RED_FLOATS 4096
#define SMEM_REC_BYTES ((US_FLOATS + HS_FLOATS + RED_FLOATS) * 4)

__global__ void __launch_bounds__(REC_THREADS, 1) lstm_rec(
    const float* __restrict__ u_f, const float* __restrict__ u_i,
    const float* __restrict__ u_c, const float* __restrict__ u_o)
{
    extern __shared__ float sm[];
    float* Us2 = sm;
    float* hsm = sm + US_FLOATS;
    float* red = sm + US_FLOATS + HS_FLOATS;
    const int tid  = threadIdx.x;
    const int lane = tid & 31;
    const int wid  = tid >> 5;       // warp == k-slice (8 slices of 128 k)
    const int cta  = blockIdx.x;

    // load + transpose this CTA's U slice
    {
        const float* umat[4] = {u_f, u_i, u_c, u_o};
        for (int i = tid; i < US_FLOATS; i += REC_THREADS) {
            int k = i >> 5, cc = i & 31;
            int gg = cc >> 3, jl = cc & 7;
            int k4 = k >> 2, j = k & 3;
            Us2[k4 * 128 + cc * 4 + j] = umat[gg][(size_t)k * H + cta * 8 + jl];
        }
    }
    __syncthreads();

    const int c2 = lane & 15;
    const int bh = lane >> 4;
    const int c0 = c2 * 2, c1 = c0 + 1;
    const int ks = wid;
    const uint32_t hsm_a = smem_u32(hsm);
    const float4* Us4 = (const float4*)Us2;
    const float4* h4  = (const float4*)hsm;
    float creg = 0.f;

    // prefetch pre-activations for t=0
    float pre[4];
    int jloc_u = tid >> 4, b_u = tid & 15;
    if (tid < 128) {
        size_t row = (size_t)(b_u * TSTEPS + 0) * N1 + cta * 8 + jloc_u;
        #pragma unroll
        for (int gg = 0; gg < 4; gg++) pre[gg] = __ldg(&g_xall[row + gg * 1024]);
    }

    for (int t = 0; t < TSTEPS; t++) {
        // per-warp stage of OWN k-slice (8 KB); no block sync needed
        {
            const float* src = g_h + ks * 2048 + lane * 4;
            uint32_t dst = hsm_a + ks * 8192 + lane * 16;
            #pragma unroll
            for (int i = 0; i < 16; i++)
                cp16(dst + i * 512, src + i * 128);
            cp_commit();
            cp_wait<0>();
            __syncwarp();
        }

        // inner product: thread owns 2 cols x 8 batches over its 128-k slice
        u64 acc[8];
        #pragma unroll
        for (int i = 0; i < 8; i++) acc[i] = 0ull;
        {
            const int k4beg = ks * 32;
            #pragma unroll 4
            for (int k4 = k4beg; k4 < k4beg + 32; k4++) {
                float4 u0 = Us4[k4 * 32 + c0];
                float4 u1 = Us4[k4 * 32 + c1];
                #pragma unroll
                for (int j = 0; j < 4; j++) {
                    int k = k4 * 4 + j;
                    float4 ha = h4[k * 4 + bh * 2];
                    float4 hb = h4[k * 4 + bh * 2 + 1];
                    u64 p0 = pk2(ha.x, ha.y), p1 = pk2(ha.z, ha.w);
                    u64 p2 = pk2(hb.x, hb.y), p3 = pk2(hb.z, hb.w);
                    float uj0 = ((const float*)&u0)[j];
                    float uj1 = ((const float*)&u1)[j];
                    u64 w0 = pk2(uj0, uj0), w1 = pk2(uj1, uj1);
                    fma2(acc[0], w0, p0); fma2(acc[1], w0, p1);
                    fma2(acc[2], w0, p2); fma2(acc[3], w0, p3);
                    fma2(acc[4], w1, p0); fma2(acc[5], w1, p1);
                    fma2(acc[6], w1, p2); fma2(acc[7], w1, p3);
                }
            }
        }
        {
            float o[16];
            #pragma unroll
            for (int i = 0; i < 8; i++) upk2(o[2*i], o[2*i+1], acc[i]);
            float* r0 = red + (ks * 32 + c0) * 16 + bh * 8;
            float* r1 = red + (ks * 32 + c1) * 16 + bh * 8;
            *(float4*)(r0)     = *(float4*)&o[0];
            *(float4*)(r0 + 4) = *(float4*)&o[4];
            *(float4*)(r1)     = *(float4*)&o[8];
            *(float4*)(r1 + 4) = *(float4*)&o[12];
        }
        __syncthreads();

        // reduce + nonlinearity + state update (128 threads)
        if (tid < 128) {
            float s[4];
            #pragma unroll
            for (int gg = 0; gg < 4; gg++) {
                int cc = gg * 8 + jloc_u;
                float v = 0.f;
                #pragma unroll
                for (int kk = 0; kk < 8; kk++) v += red[(kk * 32 + cc) * 16 + b_u];
                s[gg] = v + pre[gg];
            }
            float ft   = 1.f / (1.f + __expf(-s[0]));
            float it   = 1.f / (1.f + __expf(-s[1]));
            float cand = tanhf(s[2]);
            float ot   = 1.f / (1.f + __expf(-s[3]));
            creg = ft * creg + it * cand;
            float hv = ot * tanhf(creg);
            int jglob = cta * 8 + jloc_u;
            g_h[jglob * NB + b_u] = hv;
            g_hs[(size_t)(b_u * TSTEPS + t) * H + jglob] = hv;
        }

        // prefetch next step's pre-activations (overlaps barrier wait)
        if (tid < 128 && t + 1 < TSTEPS) {
            size_t row = (size_t)(b_u * TSTEPS + t + 1) * N1 + cta * 8 + jloc_u;
            #pragma unroll
            for (int gg = 0; gg < 4; gg++) pre[gg] = __ldg(&g_xall[row + gg * 1024]);
        }

        // grid barrier
        __syncthreads();
        if (tid == 0) {
            __threadfence();
            atomicAdd(&g_bar, 1u);
            const unsigned target = (unsigned)(REC_CTAS * (t + 1));
            int spins = 0;
            while (true) {
                unsigned v;
                asm volatile("ld.global.cg.u32 %0, [%1];" : "=r"(v) : "l"(&g_bar));
                if (v >= target) break;
                if (++spins > 8) __nanosleep(32);
            }
            __threadfence();
        }
        __syncthreads();
    }
}

__global__ void init_kernel() {
    int i = blockIdx.x * blockDim.x + threadIdx.x;
    if (i == 0) g_bar = 0u;
    if (i < H * NB) g_h[i] = 0.f;
}

// ---------------- launch ----------------------------------------------------
extern "C" void kernel_launch(void* const* d_in, const int* in_sizes, int n_in,
                              void* d_out, int out_size) {
    const int*   tokens = (const int*)d_in[0];
    const float* emb    = (const float*)d_in[1];
    const float* w_f = (const float*)d_in[2];
    const float* u_f = (const float*)d_in[3];
    const float* b_f = (const float*)d_in[4];
    const float* w_i = (const float*)d_in[5];
    const float* u_i = (const float*)d_in[6];
    const float* b_i = (const float*)d_in[7];
    const float* w_c = (const float*)d_in[8];
    const float* u_c = (const float*)d_in[9];
    const float* b_c = (const float*)d_in[10];
    const float* w_o = (const float*)d_in[11];
    const float* u_o = (const float*)d_in[12];
    const float* b_o = (const float*)d_in[13];
    const float* w_out = (const float*)d_in[14];
    const float* b_out = (const float*)d_in[15];
    float* out = (float*)d_out;

    cudaFuncSetAttribute(lstm_rec, cudaFuncAttributeMaxDynamicSharedMemorySize,
                         SMEM_REC_BYTES);
    cudaFuncSetAttribute(gemm_mma<0>, cudaFuncAttributeMaxDynamicSharedMemorySize,
                         GM_SMEM);
    cudaFuncSetAttribute(gemm_mma<1>, cudaFuncAttributeMaxDynamicSharedMemorySize,
                         GM_SMEM);

    init_kernel<<<64, 256>>>();
    conv_w2<<<(int)(((size_t)H * NV + 255) / 256), 256>>>(w_out);
    conv_w1<<<(int)(((size_t)H * N1 + 255) / 256), 256>>>(w_f, w_i, w_c, w_o,
                                                          b_f, b_i, b_c, b_o);
    conv_x<<<(int)(((size_t)BT * H + 255) / 256), 256>>>(tokens, emb);
    gemm_mma<0><<<dim3(BT / GM_BM, N1 / 128), 256, GM_SMEM>>>(nullptr, nullptr);
    lstm_rec<<<REC_CTAS, REC_THREADS, SMEM_REC_BYTES>>>(u_f, u_i, u_c, u_o);
    conv_a2<<<(int)(((size_t)BT * H + 255) / 256), 256>>>();
    gemm_mma<1><<<dim3(BT / GM_BM, NV / 128), 256, GM_SMEM>>>(b_out, out);
}